// round 1
// baseline (speedup 1.0000x reference)
#include <cuda_runtime.h>
#include <math.h>

// Problem constants (fixed by the dataset)
#define BB 2
#define TT 2048
#define CC 1024
#define HH 16
#define DD 64
#define MM (BB*TT)   // 4096 rows

// Scratch (allocation-free rule: __device__ globals)
__device__ float g_Q[BB*HH*TT*DD];   // [b,h,t,d], pre-scaled by 1/sqrt(d)
__device__ float g_K[BB*HH*TT*DD];
__device__ float g_V[BB*HH*TT*DD];
__device__ float g_Y[BB*TT*CC];      // attention output before final proj

// ---------------------------------------------------------------------------
// Tiled SGEMM: out = A[M,K] @ W[K,N] + bias, with M=4096, K=N=1024.
// MODE 0: out is row-major [M,N] (final projection, writes d_out)
// MODE 1: out is [B,H,T,D] scratch layout (QKV projections), value *= scale
// ---------------------------------------------------------------------------
template<int MODE>
__global__ __launch_bounds__(256)
void gemm_kernel(const float* __restrict__ A, const float* __restrict__ W,
                 const float* __restrict__ bias, float* __restrict__ out,
                 float scale)
{
    const int K = CC, N = CC;
    __shared__ float As[16][65];   // [k][m], +1 pad to break store conflicts
    __shared__ float Bs[16][64];   // [k][n]

    const int tid = threadIdx.x;
    const int m0 = blockIdx.y * 64;
    const int n0 = blockIdx.x * 64;
    const int ty = tid >> 4;       // 0..15 -> 4 output rows each
    const int tx = tid & 15;       // 0..15 -> 4 output cols each

    // loader mapping
    const int ar = tid >> 2;           // 0..63 row in A tile
    const int ac = (tid & 3) * 4;      // k offset (float4)
    const int br = tid >> 4;           // 0..15 k row in B tile
    const int bc = (tid & 15) * 4;     // n offset (float4)

    float acc[4][4];
    #pragma unroll
    for (int i = 0; i < 4; i++)
        #pragma unroll
        for (int j = 0; j < 4; j++) acc[i][j] = 0.f;

    for (int k0 = 0; k0 < K; k0 += 16) {
        float4 a4 = *(const float4*)&A[(m0 + ar) * K + k0 + ac];
        float4 b4 = *(const float4*)&W[(k0 + br) * N + n0 + bc];
        As[ac+0][ar] = a4.x; As[ac+1][ar] = a4.y;
        As[ac+2][ar] = a4.z; As[ac+3][ar] = a4.w;
        *(float4*)&Bs[br][bc] = b4;
        __syncthreads();
        #pragma unroll
        for (int kk = 0; kk < 16; kk++) {
            float a[4], b[4];
            #pragma unroll
            for (int i = 0; i < 4; i++) a[i] = As[kk][ty*4 + i];
            float4 bv = *(const float4*)&Bs[kk][tx*4];
            b[0] = bv.x; b[1] = bv.y; b[2] = bv.z; b[3] = bv.w;
            #pragma unroll
            for (int i = 0; i < 4; i++)
                #pragma unroll
                for (int j = 0; j < 4; j++)
                    acc[i][j] = fmaf(a[i], b[j], acc[i][j]);
        }
        __syncthreads();
    }

    #pragma unroll
    for (int i = 0; i < 4; i++) {
        int gr = m0 + ty*4 + i;
        #pragma unroll
        for (int j = 0; j < 4; j++) {
            int gc = n0 + tx*4 + j;
            float v = (acc[i][j] + bias[gc]) * scale;
            if (MODE == 0) {
                out[gr * N + gc] = v;
            } else {
                int b = gr / TT, t = gr % TT;
                int h = gc / DD, dd = gc % DD;
                out[((b*HH + h)*TT + t)*DD + dd] = v;
            }
        }
    }
}

// ---------------------------------------------------------------------------
// Flash attention (fp32, causal, online softmax).
// Grid: (T/64 query tiles, B*H). Block: 256 threads.
// Each block: 64 queries, loops KV tiles of 32 up to the causal boundary.
// Thread mapping: row = tid/4 (query row), g = tid%4.
//   - scores:   thread owns cols c = 4j+g, j=0..7   (conflict-free LDS.128)
//   - output:   thread owns dims g*16 .. g*16+15
// ---------------------------------------------------------------------------
__global__ __launch_bounds__(256)
void flash_kernel()
{
    __shared__ float Qs[64][68];   // stride 68: float4-aligned, conflict-free
    __shared__ float Ks[32][68];
    __shared__ float Vs[32][68];
    __shared__ float Ps[64][36];

    const int bh    = blockIdx.y;        // 0..31
    const int qtile = blockIdx.x;        // 0..31
    const int q0    = qtile * 64;
    const float* Qp = g_Q + (size_t)bh * TT * DD;
    const float* Kp = g_K + (size_t)bh * TT * DD;
    const float* Vp = g_V + (size_t)bh * TT * DD;

    const int tid = threadIdx.x;
    const int row = tid >> 2;            // 0..63
    const int g   = tid & 3;             // 0..3

    // load Q tile (64 x 64)
    for (int i = tid; i < 64*16; i += 256) {
        int r = i >> 4, c4 = (i & 15) * 4;
        *(float4*)&Qs[r][c4] = *(const float4*)&Qp[(q0 + r)*DD + c4];
    }

    float O[16];
    #pragma unroll
    for (int j = 0; j < 16; j++) O[j] = 0.f;
    float m = -INFINITY, l = 0.f;

    const int ktiles = (q0 + 64) / 32;   // causal bound
    for (int kt = 0; kt < ktiles; kt++) {
        const int k0 = kt * 32;
        __syncthreads();   // prior-iter readers done before overwrite (also covers Q load)
        for (int i = tid; i < 32*16; i += 256) {
            int r = i >> 4, c4 = (i & 15) * 4;
            *(float4*)&Ks[r][c4] = *(const float4*)&Kp[(k0 + r)*DD + c4];
            *(float4*)&Vs[r][c4] = *(const float4*)&Vp[(k0 + r)*DD + c4];
        }
        __syncthreads();

        // S = Q K^T for this thread's 8 columns (c = 4j+g)
        float s[8];
        #pragma unroll
        for (int j = 0; j < 8; j++) s[j] = 0.f;
        #pragma unroll
        for (int d4 = 0; d4 < 16; d4++) {
            float4 q4 = *(const float4*)&Qs[row][d4*4];
            #pragma unroll
            for (int j = 0; j < 8; j++) {
                float4 k4 = *(const float4*)&Ks[4*j + g][d4*4];
                s[j] = fmaf(q4.x, k4.x, s[j]);
                s[j] = fmaf(q4.y, k4.y, s[j]);
                s[j] = fmaf(q4.z, k4.z, s[j]);
                s[j] = fmaf(q4.w, k4.w, s[j]);
            }
        }

        // causal mask (Q already carries 1/sqrt(d))
        const int qg = q0 + row;
        #pragma unroll
        for (int j = 0; j < 8; j++) {
            int kg = k0 + 4*j + g;
            if (kg > qg) s[j] = -INFINITY;
        }

        // row max across this thread's 8 + the 4-thread row group
        float mt = s[0];
        #pragma unroll
        for (int j = 1; j < 8; j++) mt = fmaxf(mt, s[j]);
        mt = fmaxf(mt, __shfl_xor_sync(0xffffffffu, mt, 1));
        mt = fmaxf(mt, __shfl_xor_sync(0xffffffffu, mt, 2));

        const float mn    = fmaxf(m, mt);
        const float alpha = __expf(m - mn);   // exp(-inf)=0 on first tile
        float rs = 0.f;
        #pragma unroll
        for (int j = 0; j < 8; j++) {
            float p = __expf(s[j] - mn);
            Ps[row][4*j + g] = p;
            rs += p;
        }
        rs += __shfl_xor_sync(0xffffffffu, rs, 1);
        rs += __shfl_xor_sync(0xffffffffu, rs, 2);
        l = l * alpha + rs;
        m = mn;
        #pragma unroll
        for (int j = 0; j < 16; j++) O[j] *= alpha;

        __syncwarp();   // Ps row produced/consumed within one warp

        // O += P @ V  (thread owns dims g*16..g*16+15)
        #pragma unroll
        for (int c = 0; c < 32; c++) {
            float p = Ps[row][c];
            #pragma unroll
            for (int j4 = 0; j4 < 4; j4++) {
                float4 v4 = *(const float4*)&Vs[c][g*16 + j4*4];
                O[j4*4+0] = fmaf(p, v4.x, O[j4*4+0]);
                O[j4*4+1] = fmaf(p, v4.y, O[j4*4+1]);
                O[j4*4+2] = fmaf(p, v4.z, O[j4*4+2]);
                O[j4*4+3] = fmaf(p, v4.w, O[j4*4+3]);
            }
        }
    }

    // normalize and write y[b, t, h*64 + dc]
    const float inv = 1.f / l;
    const int b = bh >> 4, h = bh & 15;
    const int t = q0 + row;
    float* yp = &g_Y[((size_t)(b*TT + t))*CC + h*DD + g*16];
    #pragma unroll
    for (int j4 = 0; j4 < 4; j4++) {
        float4 v;
        v.x = O[j4*4+0] * inv; v.y = O[j4*4+1] * inv;
        v.z = O[j4*4+2] * inv; v.w = O[j4*4+3] * inv;
        *(float4*)&yp[j4*4] = v;
    }
}

// ---------------------------------------------------------------------------
// Launch: QKV GEMMs -> flash attention -> output projection
// Inputs: 0 query, 1 Wq, 2 bq, 3 Wk, 4 bk, 5 Wv, 6 bv, 7 Wp, 8 bp, 9 n_head
// ---------------------------------------------------------------------------
extern "C" void kernel_launch(void* const* d_in, const int* in_sizes, int n_in,
                              void* d_out, int out_size)
{
    const float* x  = (const float*)d_in[0];
    const float* Wq = (const float*)d_in[1];
    const float* bq = (const float*)d_in[2];
    const float* Wk = (const float*)d_in[3];
    const float* bk = (const float*)d_in[4];
    const float* Wv = (const float*)d_in[5];
    const float* bv = (const float*)d_in[6];
    const float* Wp = (const float*)d_in[7];
    const float* bp = (const float*)d_in[8];
    float* out = (float*)d_out;

    void *pQ, *pK, *pV, *pY;
    cudaGetSymbolAddress(&pQ, g_Q);
    cudaGetSymbolAddress(&pK, g_K);
    cudaGetSymbolAddress(&pV, g_V);
    cudaGetSymbolAddress(&pY, g_Y);

    dim3 gg(CC/64, MM/64);   // (16, 64)
    const float qscale = 0.125f;  // 1/sqrt(64)

    gemm_kernel<1><<<gg, 256>>>(x, Wq, bq, (float*)pQ, qscale);
    gemm_kernel<1><<<gg, 256>>>(x, Wk, bk, (float*)pK, 1.0f);
    gemm_kernel<1><<<gg, 256>>>(x, Wv, bv, (float*)pV, 1.0f);

    dim3 fg(TT/64, BB*HH);   // (32, 32)
    flash_kernel<<<fg, 256>>>();

    gemm_kernel<0><<<gg, 256>>>((const float*)pY, Wp, bp, out, 1.0f);
}

// round 5
// speedup vs baseline: 1.6060x; 1.6060x over previous
#include <cuda_runtime.h>
#include <math.h>

#define BB 2
#define TT 2048
#define CC 1024
#define HH 16
#define DD 64
#define MM (BB*TT)   // 4096

typedef unsigned long long ull;

// Scratch (allocation-free rule: __device__ globals)
__device__ float g_Q[BB*HH*TT*DD];   // [b,h,t,d], Q pre-scaled by 1/sqrt(d)
__device__ float g_K[BB*HH*TT*DD];
__device__ float g_V[BB*HH*TT*DD];
__device__ float g_Y[BB*TT*CC];

// ---- packed f32x2 helpers (Blackwell FFMA2 path) ----
__device__ __forceinline__ ull ffma2(ull a, ull b, ull c) {
    ull d; asm("fma.rn.f32x2 %0, %1, %2, %3;" : "=l"(d) : "l"(a), "l"(b), "l"(c)); return d;
}
__device__ __forceinline__ ull fmul2(ull a, ull b) {
    ull d; asm("mul.rn.f32x2 %0, %1, %2;" : "=l"(d) : "l"(a), "l"(b)); return d;
}
__device__ __forceinline__ ull packdup(float x) {
    ull r; asm("mov.b64 %0, {%1, %1};" : "=l"(r) : "f"(x)); return r;
}
__device__ __forceinline__ float lo32(ull v) { return __uint_as_float((unsigned)v); }
__device__ __forceinline__ float hi32(ull v) { return __uint_as_float((unsigned)(v >> 32)); }

// ---------------------------------------------------------------------------
// 128x128 SGEMM core, BK=16, 256 threads, 8x8 per thread, f32x2 FMAs,
// register-prefetch pipeline. MODE 0: row-major out. MODE 1: [B,H,T,D] out.
// ---------------------------------------------------------------------------
template<int MODE>
__device__ __forceinline__ void gemm_core(const float* __restrict__ A,
                                          const float* __restrict__ W,
                                          const float* __restrict__ bias,
                                          float* __restrict__ out,
                                          float scale,
                                          float* As, float* Bs)
{
    const int tid = threadIdx.x;
    const int m0 = blockIdx.y * 128;
    const int n0 = blockIdx.x * 128;
    const int ty = tid >> 4;           // 0..15 -> rows ty*8..+7
    const int tx = tid & 15;           // 0..15 -> cols tx*8..+7

    const int arow = tid >> 1;         // 0..127
    const int akc  = (tid & 1) * 8;    // 0 or 8
    const int bkr  = tid >> 4;         // 0..15
    const int bnc  = (tid & 15) * 8;   // 0..120

    ull acc[8][4];
    #pragma unroll
    for (int i = 0; i < 8; i++)
        #pragma unroll
        for (int j = 0; j < 4; j++) acc[i][j] = 0ull;

    // prefetch tile 0
    const float* Ap = A + (size_t)(m0 + arow) * CC + akc;
    const float* Wp = W + (size_t)bkr * CC + n0 + bnc;
    float4 pa0 = *(const float4*)(Ap);
    float4 pa1 = *(const float4*)(Ap + 4);
    float4 pb0 = *(const float4*)(Wp);
    float4 pb1 = *(const float4*)(Wp + 4);

    for (int kt = 0; kt < CC/16; kt++) {
        // store prefetched tile (A transposed: As[k][m], stride 132)
        As[(akc+0)*132 + arow] = pa0.x;
        As[(akc+1)*132 + arow] = pa0.y;
        As[(akc+2)*132 + arow] = pa0.z;
        As[(akc+3)*132 + arow] = pa0.w;
        As[(akc+4)*132 + arow] = pa1.x;
        As[(akc+5)*132 + arow] = pa1.y;
        As[(akc+6)*132 + arow] = pa1.z;
        As[(akc+7)*132 + arow] = pa1.w;
        *(float4*)(Bs + bkr*128 + bnc)     = pb0;
        *(float4*)(Bs + bkr*128 + bnc + 4) = pb1;
        __syncthreads();

        if (kt < CC/16 - 1) {   // issue next tile's global loads (hidden by compute)
            const float* Ap2 = A + (size_t)(m0 + arow) * CC + (kt+1)*16 + akc;
            const float* Wp2 = W + (size_t)((kt+1)*16 + bkr) * CC + n0 + bnc;
            pa0 = *(const float4*)(Ap2);
            pa1 = *(const float4*)(Ap2 + 4);
            pb0 = *(const float4*)(Wp2);
            pb1 = *(const float4*)(Wp2 + 4);
        }

        #pragma unroll
        for (int kk = 0; kk < 16; kk++) {
            float4 av0 = *(const float4*)(As + kk*132 + ty*8);
            float4 av1 = *(const float4*)(As + kk*132 + ty*8 + 4);
            ulonglong2 bA = *(const ulonglong2*)(Bs + kk*128 + tx*8);
            ulonglong2 bB = *(const ulonglong2*)(Bs + kk*128 + tx*8 + 4);
            ull b2[4] = { bA.x, bA.y, bB.x, bB.y };
            ull aa[8] = { packdup(av0.x), packdup(av0.y), packdup(av0.z), packdup(av0.w),
                          packdup(av1.x), packdup(av1.y), packdup(av1.z), packdup(av1.w) };
            #pragma unroll
            for (int i = 0; i < 8; i++)
                #pragma unroll
                for (int j = 0; j < 4; j++)
                    acc[i][j] = ffma2(aa[i], b2[j], acc[i][j]);
        }
        __syncthreads();
    }

    // epilogue
    float bl[8];
    #pragma unroll
    for (int j = 0; j < 8; j++) bl[j] = bias[n0 + tx*8 + j];

    #pragma unroll
    for (int i = 0; i < 8; i++) {
        int gr = m0 + ty*8 + i;
        float v[8];
        #pragma unroll
        for (int j = 0; j < 4; j++) {
            v[2*j]   = (lo32(acc[i][j]) + bl[2*j])   * scale;
            v[2*j+1] = (hi32(acc[i][j]) + bl[2*j+1]) * scale;
        }
        if (MODE == 0) {
            float* op = out + (size_t)gr * CC + n0 + tx*8;
            *(float4*)(op)     = make_float4(v[0], v[1], v[2], v[3]);
            *(float4*)(op + 4) = make_float4(v[4], v[5], v[6], v[7]);
        } else {
            int b = gr / TT, t = gr % TT;
            int gc0 = n0 + tx*8;
            int h = gc0 / DD, dd = gc0 % DD;   // 8 cols stay inside one head
            float* op = out + (((size_t)(b*HH + h))*TT + t)*DD + dd;
            *(float4*)(op)     = make_float4(v[0], v[1], v[2], v[3]);
            *(float4*)(op + 4) = make_float4(v[4], v[5], v[6], v[7]);
        }
    }
}

__global__ __launch_bounds__(256)
void qkv_kernel(const float* __restrict__ x,
                const float* __restrict__ Wq, const float* __restrict__ Wk,
                const float* __restrict__ Wv,
                const float* __restrict__ bq, const float* __restrict__ bk,
                const float* __restrict__ bv)
{
    __shared__ __align__(16) float As[16*132];
    __shared__ __align__(16) float Bs[16*128];
    int z = blockIdx.z;
    const float* W = (z == 0) ? Wq : (z == 1) ? Wk : Wv;
    const float* b = (z == 0) ? bq : (z == 1) ? bk : bv;
    float* o       = (z == 0) ? g_Q : (z == 1) ? g_K : g_V;
    float scale    = (z == 0) ? 0.125f : 1.0f;   // 1/sqrt(64) folded into Q
    gemm_core<1>(x, W, b, o, scale, As, Bs);
}

__global__ __launch_bounds__(256)
void proj_kernel(const float* __restrict__ Wp, const float* __restrict__ bp,
                 float* __restrict__ out)
{
    __shared__ __align__(16) float As[16*132];
    __shared__ __align__(16) float Bs[16*128];
    gemm_core<0>(g_Y, Wp, bp, out, 1.0f, As, Bs);
}

// ---------------------------------------------------------------------------
// Flash attention: 64 queries x 64-key tiles, 256 threads.
// Thread: rp = tid>>3 -> rows 2rp, 2rp+1 ; cg = tid&7.
//   QK cols: c = 8j+cg (interleaved -> conflict-free K loads, banks 4cg..)
//   PV dims: d = 8cg..8cg+7
// f32x2: QK pairs adjacent d (partial accumulators), PV pairs adjacent dims.
// ---------------------------------------------------------------------------
#define FSM_Q 0
#define FSM_K 4352      // 64*68
#define FSM_V 8704
#define FSM_P 13056
#define FLASH_SMEM ((13056 + 64*68) * 4)   // 69632 B

__global__ __launch_bounds__(256)
void flash_kernel()
{
    extern __shared__ __align__(16) float sm[];
    float* Qs = sm + FSM_Q;
    float* Ks = sm + FSM_K;
    float* Vs = sm + FSM_V;
    float* Ps = sm + FSM_P;

    const int bh    = blockIdx.y;
    const int qtile = blockIdx.x;
    const int q0    = qtile * 64;
    const float* Qp = g_Q + (size_t)bh * TT * DD;
    const float* Kp = g_K + (size_t)bh * TT * DD;
    const float* Vp = g_V + (size_t)bh * TT * DD;

    const int tid = threadIdx.x;
    const int rp  = tid >> 3;    // 0..31
    const int cg  = tid & 7;     // 0..7
    const int r0  = rp * 2;

    // load Q tile 64x64
    #pragma unroll
    for (int i = 0; i < 4; i++) {
        int idx = i*256 + tid;
        int r = idx >> 4, c4 = (idx & 15) * 4;
        *(float4*)(Qs + r*68 + c4) = *(const float4*)(Qp + (size_t)(q0 + r)*DD + c4);
    }

    ull O2[2][4] = {{0,0,0,0},{0,0,0,0}};
    float m[2] = {-INFINITY, -INFINITY};
    float l[2] = {0.f, 0.f};

    for (int kt = 0; kt <= qtile; kt++) {
        const int k0 = kt * 64;
        __syncthreads();   // covers Q load + prior-iter K/V/P readers
        #pragma unroll
        for (int i = 0; i < 4; i++) {
            int idx = i*256 + tid;
            int r = idx >> 4, c4 = (idx & 15) * 4;
            *(float4*)(Ks + r*68 + c4) = *(const float4*)(Kp + (size_t)(k0 + r)*DD + c4);
            *(float4*)(Vs + r*68 + c4) = *(const float4*)(Vp + (size_t)(k0 + r)*DD + c4);
        }
        __syncthreads();

        // ---- S = Q K^T : 2 rows x 8 interleaved cols, f32x2 over d-pairs
        ull acc[2][8];
        #pragma unroll
        for (int j = 0; j < 8; j++) { acc[0][j] = 0ull; acc[1][j] = 0ull; }

        #pragma unroll
        for (int d4 = 0; d4 < 16; d4++) {
            ulonglong2 qa = *(const ulonglong2*)(Qs + r0*68 + d4*4);
            ulonglong2 qb = *(const ulonglong2*)(Qs + (r0+1)*68 + d4*4);
            #pragma unroll
            for (int j = 0; j < 8; j++) {
                ulonglong2 kv = *(const ulonglong2*)(Ks + (j*8 + cg)*68 + d4*4);
                acc[0][j] = ffma2(qa.x, kv.x, acc[0][j]);
                acc[0][j] = ffma2(qa.y, kv.y, acc[0][j]);
                acc[1][j] = ffma2(qb.x, kv.x, acc[1][j]);
                acc[1][j] = ffma2(qb.y, kv.y, acc[1][j]);
            }
        }

        // ---- online softmax per row
        const bool diag = (kt == qtile);
        #pragma unroll
        for (int i = 0; i < 2; i++) {
            const int qg = q0 + r0 + i;
            float s[8];
            #pragma unroll
            for (int j = 0; j < 8; j++) s[j] = lo32(acc[i][j]) + hi32(acc[i][j]);
            if (diag) {
                #pragma unroll
                for (int j = 0; j < 8; j++)
                    if (k0 + j*8 + cg > qg) s[j] = -INFINITY;
            }
            float mt = s[0];
            #pragma unroll
            for (int j = 1; j < 8; j++) mt = fmaxf(mt, s[j]);
            mt = fmaxf(mt, __shfl_xor_sync(0xffffffffu, mt, 1));
            mt = fmaxf(mt, __shfl_xor_sync(0xffffffffu, mt, 2));
            mt = fmaxf(mt, __shfl_xor_sync(0xffffffffu, mt, 4));

            float mn = fmaxf(m[i], mt);
            float alpha = __expf(m[i] - mn);
            float rs = 0.f;
            #pragma unroll
            for (int j = 0; j < 8; j++) {
                float p = __expf(s[j] - mn);
                Ps[(r0 + i)*68 + j*8 + cg] = p;
                rs += p;
            }
            rs += __shfl_xor_sync(0xffffffffu, rs, 1);
            rs += __shfl_xor_sync(0xffffffffu, rs, 2);
            rs += __shfl_xor_sync(0xffffffffu, rs, 4);
            l[i] = l[i] * alpha + rs;
            m[i] = mn;
            ull al2 = packdup(alpha);
            #pragma unroll
            for (int j = 0; j < 4; j++) O2[i][j] = fmul2(al2, O2[i][j]);
        }

        __syncwarp();   // Ps produced/consumed within one 8-lane row group

        // ---- O += P @ V : 2 rows x 8 dims per thread
        #pragma unroll 4
        for (int c = 0; c < 64; c++) {
            float p0 = Ps[r0*68 + c];
            float p1 = Ps[(r0+1)*68 + c];
            ull pp0 = packdup(p0), pp1 = packdup(p1);
            ulonglong2 vA = *(const ulonglong2*)(Vs + c*68 + cg*8);
            ulonglong2 vB = *(const ulonglong2*)(Vs + c*68 + cg*8 + 4);
            O2[0][0] = ffma2(pp0, vA.x, O2[0][0]);
            O2[0][1] = ffma2(pp0, vA.y, O2[0][1]);
            O2[0][2] = ffma2(pp0, vB.x, O2[0][2]);
            O2[0][3] = ffma2(pp0, vB.y, O2[0][3]);
            O2[1][0] = ffma2(pp1, vA.x, O2[1][0]);
            O2[1][1] = ffma2(pp1, vA.y, O2[1][1]);
            O2[1][2] = ffma2(pp1, vB.x, O2[1][2]);
            O2[1][3] = ffma2(pp1, vB.y, O2[1][3]);
        }
    }

    // epilogue: y[b, t, h*64 + 8cg .. +7]
    const int b = bh >> 4, h = bh & 15;
    #pragma unroll
    for (int i = 0; i < 2; i++) {
        int t = q0 + r0 + i;
        float inv = 1.f / l[i];
        float o[8];
        #pragma unroll
        for (int j = 0; j < 4; j++) {
            o[2*j]   = lo32(O2[i][j]) * inv;
            o[2*j+1] = hi32(O2[i][j]) * inv;
        }
        float* yp = g_Y + ((size_t)(b*TT + t))*CC + h*DD + cg*8;
        *(float4*)(yp)     = make_float4(o[0], o[1], o[2], o[3]);
        *(float4*)(yp + 4) = make_float4(o[4], o[5], o[6], o[7]);
    }
}

// ---------------------------------------------------------------------------
extern "C" void kernel_launch(void* const* d_in, const int* in_sizes, int n_in,
                              void* d_out, int out_size)
{
    const float* x  = (const float*)d_in[0];
    const float* Wq = (const float*)d_in[1];
    const float* bq = (const float*)d_in[2];
    const float* Wk = (const float*)d_in[3];
    const float* bk = (const float*)d_in[4];
    const float* Wv = (const float*)d_in[5];
    const float* bv = (const float*)d_in[6];
    const float* Wp = (const float*)d_in[7];
    const float* bp = (const float*)d_in[8];
    float* out = (float*)d_out;

    cudaFuncSetAttribute(flash_kernel,
                         cudaFuncAttributeMaxDynamicSharedMemorySize, FLASH_SMEM);

    dim3 gq(CC/128, MM/128, 3);     // (8, 32, 3) = 768 blocks
    qkv_kernel<<<gq, 256>>>(x, Wq, Wk, Wv, bq, bk, bv);

    dim3 fg(TT/64, BB*HH);          // (32, 32)
    flash_kernel<<<fg, 256, FLASH_SMEM>>>();

    dim3 gp(CC/128, MM/128);        // (8, 32)
    proj_kernel<<<gp, 256>>>(Wp, bp, out);
}

// round 12
// speedup vs baseline: 2.1387x; 1.3316x over previous
#include <cuda_runtime.h>
#include <math.h>
#include <stdint.h>

#define BB 2
#define TT 2048
#define CC 1024
#define HH 16
#define DD 64
#define MM (BB*TT)   // 4096

typedef unsigned long long ull;

// Scratch (allocation-free rule: __device__ globals)
__device__ float g_Q[BB*HH*TT*DD];   // [b,h,t,d], Q pre-scaled by 1/sqrt(d)
__device__ float g_K[BB*HH*TT*DD];
__device__ float g_V[BB*HH*TT*DD];
__device__ float g_Y[BB*TT*CC];      // attention output (tf32-rounded at write)
__device__ float g_X[MM*CC];         // input x rounded to tf32
__device__ float g_WT[4*CC*CC];      // transposed weights [n][k], tf32-rounded

// ---- packed f32x2 helpers (flash kernel) ----
__device__ __forceinline__ ull ffma2(ull a, ull b, ull c) {
    ull d; asm("fma.rn.f32x2 %0, %1, %2, %3;" : "=l"(d) : "l"(a), "l"(b), "l"(c)); return d;
}
__device__ __forceinline__ ull fmul2(ull a, ull b) {
    ull d; asm("mul.rn.f32x2 %0, %1, %2;" : "=l"(d) : "l"(a), "l"(b)); return d;
}
__device__ __forceinline__ ull packdup(float x) {
    ull r; asm("mov.b64 %0, {%1, %1};" : "=l"(r) : "f"(x)); return r;
}
__device__ __forceinline__ float lo32(ull v) { return __uint_as_float((unsigned)v); }
__device__ __forceinline__ float hi32(ull v) { return __uint_as_float((unsigned)(v >> 32)); }

// ---- tf32 / mma.sync / cp.async helpers (all plain sm_80+ PTX) ----
__device__ __forceinline__ float to_tf32(float x) {
    float r; asm("cvt.rna.tf32.f32 %0, %1;" : "=f"(r) : "f"(x)); return r;
}
__device__ __forceinline__ uint32_t smem_u32(const void* p) {
    uint32_t a;
    asm("{ .reg .u64 t; cvta.to.shared.u64 t, %1; cvt.u32.u64 %0, t; }" : "=r"(a) : "l"(p));
    return a;
}
__device__ __forceinline__ void mma_tf32(float* d, const uint32_t* a,
                                         uint32_t b0, uint32_t b1) {
    asm volatile("mma.sync.aligned.m16n8k8.row.col.f32.tf32.tf32.f32 "
                 "{%0,%1,%2,%3}, {%4,%5,%6,%7}, {%8,%9}, {%0,%1,%2,%3};"
                 : "+f"(d[0]), "+f"(d[1]), "+f"(d[2]), "+f"(d[3])
                 : "r"(a[0]), "r"(a[1]), "r"(a[2]), "r"(a[3]), "r"(b0), "r"(b1));
}
#define CP_A16(dst, src) \
    asm volatile("cp.async.cg.shared.global [%0], [%1], 16;" :: "r"(dst), "l"(src))
#define CP_COMMIT() asm volatile("cp.async.commit_group;" ::: "memory")
#define CP_WAIT1()  asm volatile("cp.async.wait_group 1;" ::: "memory")
#define CP_WAIT0()  asm volatile("cp.async.wait_group 0;" ::: "memory")

// ---------------------------------------------------------------------------
// x -> g_X, rounded to tf32. grid 4096 x 256 thr, 4 floats/thread.
// ---------------------------------------------------------------------------
__global__ __launch_bounds__(256)
void cvt_x_kernel(const float* __restrict__ x)
{
    int i = (blockIdx.x * 256 + threadIdx.x) * 4;
    float4 v = *(const float4*)(x + i);
    v.x = to_tf32(v.x); v.y = to_tf32(v.y);
    v.z = to_tf32(v.z); v.w = to_tf32(v.w);
    *(float4*)(g_X + i) = v;
}

// ---------------------------------------------------------------------------
// Weight transpose + tf32 round: g_WT[z][n][k] = tf32(W_z[k][n])
// ---------------------------------------------------------------------------
__global__ __launch_bounds__(256)
void transpose_kernel(const float* __restrict__ W0, const float* __restrict__ W1,
                      const float* __restrict__ W2, const float* __restrict__ W3)
{
    __shared__ float t[32][33];
    const float* in = (blockIdx.z == 0) ? W0 : (blockIdx.z == 1) ? W1 :
                      (blockIdx.z == 2) ? W2 : W3;
    float* out = g_WT + (size_t)blockIdx.z * CC * CC;
    int nx = blockIdx.x * 32, ky = blockIdx.y * 32;
    int tx = threadIdx.x & 31, ty = threadIdx.x >> 5;   // 32 x 8
    #pragma unroll
    for (int j = 0; j < 4; j++)
        t[ty + j*8][tx] = in[(size_t)(ky + ty + j*8) * CC + nx + tx];
    __syncthreads();
    #pragma unroll
    for (int j = 0; j < 4; j++)
        out[(size_t)(nx + ty + j*8) * CC + ky + tx] = to_tf32(t[tx][ty + j*8]);
}

// ---------------------------------------------------------------------------
// tf32 mma.sync GEMM: out[m][n] = (sum_k A[m][k]*Wt[n][k] + bias[n]) * scale
// 128x128 CTA tile, BK=32, 8 warps (2x4), warp tile 64x32 (4x4 m16n8k8).
// SMEM stride 36 -> conflict-free scalar fragment loads (bank = 4*row+k).
// cp.async double-buffered pipeline. MODE 0: row-major; MODE 1: [B,H,T,D].
// ---------------------------------------------------------------------------
#define GEMM_SMEM 73728   // 2 stages * (A 128*36 + B 128*36) floats * 4B

template<int MODE>
__device__ __forceinline__ void tc_gemm_core(const float* __restrict__ A,
                                             const float* __restrict__ Wt,
                                             const float* __restrict__ bias,
                                             float* __restrict__ out, float scale)
{
    extern __shared__ __align__(16) float sm[];
    // float offsets: A0=0, B0=4608, A1=9216, B1=13824
    const int tid  = threadIdx.x;
    const int wid  = tid >> 5, lane = tid & 31;
    const int wm   = wid >> 2, wn   = wid & 3;
    const int g    = lane >> 2, t   = lane & 3;
    const int m0   = blockIdx.y * 128, n0 = blockIdx.x * 128;

    // loader mapping: 2 threads per row, 16 floats each
    const int r  = tid >> 1;
    const int cb = (tid & 1) * 16;

    const uint32_t sbase = smem_u32(sm);
    const uint32_t sAd[2] = { sbase,             sbase + 9216u*4u };
    const uint32_t sBd[2] = { sbase + 4608u*4u,  sbase + 13824u*4u };
    const uint32_t soff = (uint32_t)((r*36 + cb) * 4);

    const float* Ap = A  + (size_t)(m0 + r) * CC + cb;
    const float* Bp = Wt + (size_t)(n0 + r) * CC + cb;

    float acc[4][4][4];
    #pragma unroll
    for (int i = 0; i < 4; i++)
        #pragma unroll
        for (int j = 0; j < 4; j++)
            #pragma unroll
            for (int e = 0; e < 4; e++) acc[i][j][e] = 0.f;

    // prologue: issue tiles 0 and 1
    #pragma unroll
    for (int j = 0; j < 4; j++) {
        CP_A16(sAd[0] + soff + 16*j, Ap + 4*j);
        CP_A16(sBd[0] + soff + 16*j, Bp + 4*j);
    }
    CP_COMMIT();
    #pragma unroll
    for (int j = 0; j < 4; j++) {
        CP_A16(sAd[1] + soff + 16*j, Ap + 32 + 4*j);
        CP_A16(sBd[1] + soff + 16*j, Bp + 32 + 4*j);
    }
    CP_COMMIT();

    const int NT = CC / 32;   // 32
    for (int kt = 0; kt < NT; kt++) {
        const int p = kt & 1;
        if (kt < NT - 2) { CP_WAIT1(); } else { CP_WAIT0(); }
        __syncthreads();

        const float* As = sm + (p ? 9216 : 0);
        const float* Bs = sm + (p ? 13824 : 4608);

        #pragma unroll
        for (int ks = 0; ks < 4; ks++) {
            const int k0 = ks * 8;
            uint32_t afr[4][4];
            #pragma unroll
            for (int mt = 0; mt < 4; mt++) {
                const int ra = wm*64 + mt*16;
                afr[mt][0] = __float_as_uint(As[(ra+g  )*36 + k0 + t    ]);
                afr[mt][1] = __float_as_uint(As[(ra+g+8)*36 + k0 + t    ]);
                afr[mt][2] = __float_as_uint(As[(ra+g  )*36 + k0 + t + 4]);
                afr[mt][3] = __float_as_uint(As[(ra+g+8)*36 + k0 + t + 4]);
            }
            #pragma unroll
            for (int nt = 0; nt < 4; nt++) {
                const int rb = wn*32 + nt*8;
                uint32_t b0 = __float_as_uint(Bs[(rb+g)*36 + k0 + t    ]);
                uint32_t b1 = __float_as_uint(Bs[(rb+g)*36 + k0 + t + 4]);
                #pragma unroll
                for (int mt = 0; mt < 4; mt++)
                    mma_tf32(acc[mt][nt], afr[mt], b0, b1);
            }
        }
        __syncthreads();

        if (kt + 2 < NT) {   // refill buffer p with tile kt+2
            const int k0n = (kt + 2) * 32;
            #pragma unroll
            for (int j = 0; j < 4; j++) {
                CP_A16(sAd[p] + soff + 16*j, Ap + k0n + 4*j);
                CP_A16(sBd[p] + soff + 16*j, Bp + k0n + 4*j);
            }
            CP_COMMIT();
        }
    }

    // epilogue
    #pragma unroll
    for (int nt = 0; nt < 4; nt++) {
        const int gc = n0 + wn*32 + nt*8 + 2*t;
        const float b0 = bias[gc], b1 = bias[gc + 1];
        #pragma unroll
        for (int mt = 0; mt < 4; mt++) {
            const int gr0 = m0 + wm*64 + mt*16 + g;
            float v00 = (acc[mt][nt][0] + b0) * scale;
            float v01 = (acc[mt][nt][1] + b1) * scale;
            float v10 = (acc[mt][nt][2] + b0) * scale;
            float v11 = (acc[mt][nt][3] + b1) * scale;
            if (MODE == 0) {
                *(float2*)&out[(size_t)gr0 * CC + gc]       = make_float2(v00, v01);
                *(float2*)&out[(size_t)(gr0 + 8) * CC + gc] = make_float2(v10, v11);
            } else {
                const int h = gc >> 6, dd = gc & 63;
                const int b_ = gr0 >> 11, tt0 = gr0 & 2047;   // blocks never straddle batch
                float* base = out + (((size_t)(b_*HH + h))*TT) * DD + dd;
                *(float2*)&base[(size_t)tt0 * DD]       = make_float2(v00, v01);
                *(float2*)&base[(size_t)(tt0 + 8) * DD] = make_float2(v10, v11);
            }
        }
    }
}

__global__ __launch_bounds__(256)
void qkv_tc_kernel(const float* __restrict__ bq, const float* __restrict__ bk,
                   const float* __restrict__ bv)
{
    int z = blockIdx.z;
    const float* Wt = g_WT + (size_t)z * CC * CC;
    const float* b  = (z == 0) ? bq : (z == 1) ? bk : bv;
    float* o        = (z == 0) ? g_Q : (z == 1) ? g_K : g_V;
    float scale     = (z == 0) ? 0.125f : 1.0f;   // 1/sqrt(64) folded into Q
    tc_gemm_core<1>(g_X, Wt, b, o, scale);
}

__global__ __launch_bounds__(256)
void proj_tc_kernel(const float* __restrict__ bp, float* __restrict__ out)
{
    tc_gemm_core<0>(g_Y, g_WT + (size_t)3 * CC * CC, bp, out, 1.0f);
}

// ---------------------------------------------------------------------------
// Flash attention (FFMA2, 64q x 64k tiles, 256 threads) — unchanged except
// the g_Y write is tf32-rounded (feeds the tf32 proj GEMM anyway).
// ---------------------------------------------------------------------------
#define FSM_Q 0
#define FSM_K 4352
#define FSM_V 8704
#define FSM_P 13056
#define FLASH_SMEM ((13056 + 64*68) * 4)   // 69632 B

__global__ __launch_bounds__(256)
void flash_kernel()
{
    extern __shared__ __align__(16) float sm[];
    float* Qs = sm + FSM_Q;
    float* Ks = sm + FSM_K;
    float* Vs = sm + FSM_V;
    float* Ps = sm + FSM_P;

    const int bh    = blockIdx.y;
    const int qtile = blockIdx.x;
    const int q0    = qtile * 64;
    const float* Qp = g_Q + (size_t)bh * TT * DD;
    const float* Kp = g_K + (size_t)bh * TT * DD;
    const float* Vp = g_V + (size_t)bh * TT * DD;

    const int tid = threadIdx.x;
    const int rp  = tid >> 3;
    const int cg  = tid & 7;
    const int r0  = rp * 2;

    #pragma unroll
    for (int i = 0; i < 4; i++) {
        int idx = i*256 + tid;
        int r = idx >> 4, c4 = (idx & 15) * 4;
        *(float4*)(Qs + r*68 + c4) = *(const float4*)(Qp + (size_t)(q0 + r)*DD + c4);
    }

    ull O2[2][4] = {{0,0,0,0},{0,0,0,0}};
    float m[2] = {-INFINITY, -INFINITY};
    float l[2] = {0.f, 0.f};

    for (int kt = 0; kt <= qtile; kt++) {
        const int k0 = kt * 64;
        __syncthreads();
        #pragma unroll
        for (int i = 0; i < 4; i++) {
            int idx = i*256 + tid;
            int r = idx >> 4, c4 = (idx & 15) * 4;
            *(float4*)(Ks + r*68 + c4) = *(const float4*)(Kp + (size_t)(k0 + r)*DD + c4);
            *(float4*)(Vs + r*68 + c4) = *(const float4*)(Vp + (size_t)(k0 + r)*DD + c4);
        }
        __syncthreads();

        ull acc[2][8];
        #pragma unroll
        for (int j = 0; j < 8; j++) { acc[0][j] = 0ull; acc[1][j] = 0ull; }

        #pragma unroll
        for (int d4 = 0; d4 < 16; d4++) {
            ulonglong2 qa = *(const ulonglong2*)(Qs + r0*68 + d4*4);
            ulonglong2 qb = *(const ulonglong2*)(Qs + (r0+1)*68 + d4*4);
            #pragma unroll
            for (int j = 0; j < 8; j++) {
                ulonglong2 kv = *(const ulonglong2*)(Ks + (j*8 + cg)*68 + d4*4);
                acc[0][j] = ffma2(qa.x, kv.x, acc[0][j]);
                acc[0][j] = ffma2(qa.y, kv.y, acc[0][j]);
                acc[1][j] = ffma2(qb.x, kv.x, acc[1][j]);
                acc[1][j] = ffma2(qb.y, kv.y, acc[1][j]);
            }
        }

        const bool diag = (kt == qtile);
        #pragma unroll
        for (int i = 0; i < 2; i++) {
            const int qg = q0 + r0 + i;
            float s[8];
            #pragma unroll
            for (int j = 0; j < 8; j++) s[j] = lo32(acc[i][j]) + hi32(acc[i][j]);
            if (diag) {
                #pragma unroll
                for (int j = 0; j < 8; j++)
                    if (k0 + j*8 + cg > qg) s[j] = -INFINITY;
            }
            float mt = s[0];
            #pragma unroll
            for (int j = 1; j < 8; j++) mt = fmaxf(mt, s[j]);
            mt = fmaxf(mt, __shfl_xor_sync(0xffffffffu, mt, 1));
            mt = fmaxf(mt, __shfl_xor_sync(0xffffffffu, mt, 2));
            mt = fmaxf(mt, __shfl_xor_sync(0xffffffffu, mt, 4));

            float mn = fmaxf(m[i], mt);
            float alpha = __expf(m[i] - mn);
            float rs = 0.f;
            #pragma unroll
            for (int j = 0; j < 8; j++) {
                float p = __expf(s[j] - mn);
                Ps[(r0 + i)*68 + j*8 + cg] = p;
                rs += p;
            }
            rs += __shfl_xor_sync(0xffffffffu, rs, 1);
            rs += __shfl_xor_sync(0xffffffffu, rs, 2);
            rs += __shfl_xor_sync(0xffffffffu, rs, 4);
            l[i] = l[i] * alpha + rs;
            m[i] = mn;
            ull al2 = packdup(alpha);
            #pragma unroll
            for (int j = 0; j < 4; j++) O2[i][j] = fmul2(al2, O2[i][j]);
        }

        __syncwarp();

        #pragma unroll 4
        for (int c = 0; c < 64; c++) {
            float p0 = Ps[r0*68 + c];
            float p1 = Ps[(r0+1)*68 + c];
            ull pp0 = packdup(p0), pp1 = packdup(p1);
            ulonglong2 vA = *(const ulonglong2*)(Vs + c*68 + cg*8);
            ulonglong2 vB = *(const ulonglong2*)(Vs + c*68 + cg*8 + 4);
            O2[0][0] = ffma2(pp0, vA.x, O2[0][0]);
            O2[0][1] = ffma2(pp0, vA.y, O2[0][1]);
            O2[0][2] = ffma2(pp0, vB.x, O2[0][2]);
            O2[0][3] = ffma2(pp0, vB.y, O2[0][3]);
            O2[1][0] = ffma2(pp1, vA.x, O2[1][0]);
            O2[1][1] = ffma2(pp1, vA.y, O2[1][1]);
            O2[1][2] = ffma2(pp1, vB.x, O2[1][2]);
            O2[1][3] = ffma2(pp1, vB.y, O2[1][3]);
        }
    }

    const int b = bh >> 4, h = bh & 15;
    #pragma unroll
    for (int i = 0; i < 2; i++) {
        int t = q0 + r0 + i;
        float inv = 1.f / l[i];
        float o[8];
        #pragma unroll
        for (int j = 0; j < 4; j++) {
            o[2*j]   = to_tf32(lo32(O2[i][j]) * inv);
            o[2*j+1] = to_tf32(hi32(O2[i][j]) * inv);
        }
        float* yp = g_Y + ((size_t)(b*TT + t))*CC + h*DD + cg*8;
        *(float4*)(yp)     = make_float4(o[0], o[1], o[2], o[3]);
        *(float4*)(yp + 4) = make_float4(o[4], o[5], o[6], o[7]);
    }
}

// ---------------------------------------------------------------------------
extern "C" void kernel_launch(void* const* d_in, const int* in_sizes, int n_in,
                              void* d_out, int out_size)
{
    const float* x  = (const float*)d_in[0];
    const float* Wq = (const float*)d_in[1];
    const float* bq = (const float*)d_in[2];
    const float* Wk = (const float*)d_in[3];
    const float* bk = (const float*)d_in[4];
    const float* Wv = (const float*)d_in[5];
    const float* bv = (const float*)d_in[6];
    const float* Wp = (const float*)d_in[7];
    const float* bp = (const float*)d_in[8];
    float* out = (float*)d_out;

    cudaFuncSetAttribute(flash_kernel,
                         cudaFuncAttributeMaxDynamicSharedMemorySize, FLASH_SMEM);
    cudaFuncSetAttribute(qkv_tc_kernel,
                         cudaFuncAttributeMaxDynamicSharedMemorySize, GEMM_SMEM);
    cudaFuncSetAttribute(proj_tc_kernel,
                         cudaFuncAttributeMaxDynamicSharedMemorySize, GEMM_SMEM);

    cvt_x_kernel<<<MM*CC/1024, 256>>>(x);

    dim3 tg(32, 32, 4);
    transpose_kernel<<<tg, 256>>>(Wq, Wk, Wv, Wp);

    dim3 gq(CC/128, MM/128, 3);     // (8, 32, 3)
    qkv_tc_kernel<<<gq, 256, GEMM_SMEM>>>(bq, bk, bv);

    dim3 fg(TT/64, BB*HH);          // (32, 32)
    flash_kernel<<<fg, 256, FLASH_SMEM>>>();

    dim3 gp(CC/128, MM/128);        // (8, 32)
    proj_tc_kernel<<<gp, 256, GEMM_SMEM>>>(bp, out);
}